// round 1
// baseline (speedup 1.0000x reference)
#include <cuda_runtime.h>
#include <cstdint>

// Problem constants
#define NB   8
#define NH   8
#define SEQ  2048
#define HD   64
#define EMB  512
#define BH   (NB * NH)          // 64 (b,h) pairs
#define NROWS (BH * SEQ)        // 131072 projection rows

#define PITCH 68                // smem pitch in floats (conflict-free frags, 16B aligned)
#define P4    17                // pitch in float4

// Scratch (allocation-free rule: __device__ globals)
static __device__ __align__(256) float g_QP[BH * SEQ * HD];   // 32 MB  [bh][l][f]
static __device__ __align__(256) float g_KP[BH * SEQ * HD];   // 32 MB  [bh][l][f]
static __device__ __align__(256) float g_VP[BH * SEQ * HD];   // 32 MB  [bh][l][f]
static __device__ __align__(256) float g_AO[NB * SEQ * EMB];  // 32 MB  [b][l][e]

// round fp32 -> tf32 (rna) so the mma truncation is exact
__device__ __forceinline__ float tf32r(float x) {
    uint32_t u;
    asm("cvt.rna.tf32.f32 %0, %1;" : "=r"(u) : "f"(x));
    return __uint_as_float(u);
}

// D += A(16x8,row) * B(8x8,col), tf32 inputs, f32 accum
__device__ __forceinline__ void mma8(float& c0, float& c1, float& c2, float& c3,
                                     float a0, float a1, float a2, float a3,
                                     float b0, float b1) {
    uint32_t ua0 = __float_as_uint(a0), ua1 = __float_as_uint(a1);
    uint32_t ua2 = __float_as_uint(a2), ua3 = __float_as_uint(a3);
    uint32_t ub0 = __float_as_uint(b0), ub1 = __float_as_uint(b1);
    asm volatile(
        "mma.sync.aligned.m16n8k8.row.col.f32.tf32.tf32.f32 "
        "{%0,%1,%2,%3}, {%4,%5,%6,%7}, {%8,%9}, {%0,%1,%2,%3};\n"
        : "+f"(c0), "+f"(c1), "+f"(c2), "+f"(c3)
        : "r"(ua0), "r"(ua1), "r"(ua2), "r"(ua3), "r"(ub0), "r"(ub1));
}

// ---------------------------------------------------------------------------
// Kernel 1: Q/K/V projections (64x64 per row-chunk), fp32 SIMT.
//   q/k: input rows contiguous at ((b*H+h)*L + l)*64  (the reshape quirk)
//   v:   input row at (b*L+l)*512 + h*64 ; output re-laid to [bh][l][64]
// grid: (NROWS/64, 3), block 256
// ---------------------------------------------------------------------------
__global__ __launch_bounds__(256) void proj_kernel(
    const float* __restrict__ Qin, const float* __restrict__ Kin,
    const float* __restrict__ Vin,
    const float* __restrict__ Wq, const float* __restrict__ Wk,
    const float* __restrict__ Wv)
{
    __shared__ float Ws[64 * PITCH];
    __shared__ float Xs[64 * PITCH];

    const int tid   = threadIdx.x;
    const int which = blockIdx.y;            // 0=q 1=k 2=v
    const float* W  = (which == 0) ? Wq : (which == 1) ? Wk : Wv;
    float* Out      = (which == 0) ? g_QP : (which == 1) ? g_KP : g_VP;

    const int r0 = blockIdx.x * 64;          // first global row of this block

    // load W (64x64) into smem, coalesced
    const float4* W4 = (const float4*)W;
    #pragma unroll
    for (int i = 0; i < 4; ++i) {
        int g = tid + i * 256;               // 0..1023 float4
        ((float4*)Ws)[(g >> 4) * P4 + (g & 15)] = W4[g];
    }
    // load X tile (64 rows x 64)
    if (which < 2) {
        const float4* X4 = (const float4*)((which == 0 ? Qin : Kin) + (size_t)r0 * HD);
        #pragma unroll
        for (int i = 0; i < 4; ++i) {
            int g = tid + i * 256;
            ((float4*)Xs)[(g >> 4) * P4 + (g & 15)] = X4[g];
        }
    } else {
        const int bh = r0 >> 11;             // r0 / SEQ  (64 | SEQ so block stays in one head)
        const int l0 = r0 & 2047;
        const int b  = bh >> 3, h = bh & 7;
        const float* base = Vin + ((size_t)(b * SEQ + l0)) * EMB + h * HD;
        #pragma unroll
        for (int i = 0; i < 4; ++i) {
            int g = tid + i * 256;
            int r = g >> 4, c4 = g & 15;
            ((float4*)Xs)[r * P4 + c4] = *(const float4*)(base + (size_t)r * EMB + c4 * 4);
        }
    }
    __syncthreads();

    // compute: thread = (row-group rg: 2 rows) x (out-group og: 8 outs)
    const int rg = tid >> 3;                 // 0..31
    const int og = tid & 7;                  // 0..7
    float acc[2][8];
    #pragma unroll
    for (int i = 0; i < 2; ++i)
        #pragma unroll
        for (int f = 0; f < 8; ++f) acc[i][f] = 0.f;

    const float4* Xs4 = (const float4*)Xs;
    const float4* Ws4 = (const float4*)Ws;
    #pragma unroll
    for (int j4 = 0; j4 < 16; ++j4) {
        float4 a0 = Xs4[(rg * 2 + 0) * P4 + j4];
        float4 a1 = Xs4[(rg * 2 + 1) * P4 + j4];
        #pragma unroll
        for (int f = 0; f < 8; ++f) {
            float4 w = Ws4[(og * 8 + f) * P4 + j4];
            acc[0][f] += a0.x * w.x + a0.y * w.y + a0.z * w.z + a0.w * w.w;
            acc[1][f] += a1.x * w.x + a1.y * w.y + a1.z * w.z + a1.w * w.w;
        }
    }
    // store (rows contiguous, cols og*8..og*8+7)
    #pragma unroll
    for (int i = 0; i < 2; ++i) {
        float* op = Out + (size_t)(r0 + rg * 2 + i) * HD + og * 8;
        *(float4*)(op)     = make_float4(acc[i][0], acc[i][1], acc[i][2], acc[i][3]);
        *(float4*)(op + 4) = make_float4(acc[i][4], acc[i][5], acc[i][6], acc[i][7]);
    }
}

// ---------------------------------------------------------------------------
// Kernel 2: flash attention, Br=Bc=64, 4 warps (2x2), TF32 mma.
// grid: (SEQ/64, BH), block 128, dynamic smem 70400 B
// ---------------------------------------------------------------------------
__global__ __launch_bounds__(128) void attn_kernel()
{
    extern __shared__ float sm[];
    float* Qs   = sm;                        // 64 x PITCH
    float* Ks   = Qs + 64 * PITCH;
    float* Vs   = Ks + 64 * PITCH;
    float* Ss   = Vs + 64 * PITCH;
    float* mrow = Ss + 64 * PITCH;           // 64
    float* lrow = mrow + 64;                 // 64
    float* crow = lrow + 64;                 // 64

    const int tid  = threadIdx.x;
    const int lane = tid & 31, wid = tid >> 5;
    const int wm = wid >> 1, wn = wid & 1;   // warp tile (32x32) within 64x64
    const int gid = lane >> 2, qid = lane & 3;
    const int bh = blockIdx.y;
    const int q0 = blockIdx.x * 64;
    const float scale = 0.044194173824159216f;   // 1/sqrt(512)

    // Q tile (tf32-rounded)
    const float4* Qg = (const float4*)(g_QP + (size_t)(bh * SEQ + q0) * HD);
    #pragma unroll
    for (int i = 0; i < 8; ++i) {
        int g = tid + i * 128;               // 0..1023
        float4 v = Qg[g];
        v.x = tf32r(v.x); v.y = tf32r(v.y); v.z = tf32r(v.z); v.w = tf32r(v.w);
        ((float4*)Qs)[(g >> 4) * P4 + (g & 15)] = v;
    }
    if (tid < 64) { mrow[tid] = -1e30f; lrow[tid] = 0.f; }

    float o[2][4][4];
    #pragma unroll
    for (int mi = 0; mi < 2; ++mi)
        #pragma unroll
        for (int ni = 0; ni < 4; ++ni)
            #pragma unroll
            for (int t = 0; t < 4; ++t) o[mi][ni][t] = 0.f;

    for (int kt = 0; kt < SEQ / 64; ++kt) {
        __syncthreads();   // previous tile's PV reads done (also orders Q store / m,l init)

        // load K,V tiles (tf32-rounded); rows contiguous in [bh][l][64] layout
        const float4* Kg = (const float4*)(g_KP + (size_t)(bh * SEQ + kt * 64) * HD);
        const float4* Vg = (const float4*)(g_VP + (size_t)(bh * SEQ + kt * 64) * HD);
        #pragma unroll
        for (int i = 0; i < 8; ++i) {
            int g = tid + i * 128;
            int off = (g >> 4) * P4 + (g & 15);
            float4 kv = Kg[g];
            kv.x = tf32r(kv.x); kv.y = tf32r(kv.y); kv.z = tf32r(kv.z); kv.w = tf32r(kv.w);
            ((float4*)Ks)[off] = kv;
            float4 vv = Vg[g];
            vv.x = tf32r(vv.x); vv.y = tf32r(vv.y); vv.z = tf32r(vv.z); vv.w = tf32r(vv.w);
            ((float4*)Vs)[off] = vv;
        }
        __syncthreads();

        // S = Q * K^T (64x64x64)
        float sacc[2][4][4];
        #pragma unroll
        for (int mi = 0; mi < 2; ++mi)
            #pragma unroll
            for (int ni = 0; ni < 4; ++ni)
                #pragma unroll
                for (int t = 0; t < 4; ++t) sacc[mi][ni][t] = 0.f;

        #pragma unroll
        for (int ks = 0; ks < 8; ++ks) {
            float a[2][4];
            #pragma unroll
            for (int mi = 0; mi < 2; ++mi) {
                int r = 32 * wm + 16 * mi + gid;
                int c = ks * 8 + qid;
                a[mi][0] = Qs[r * PITCH + c];
                a[mi][1] = Qs[(r + 8) * PITCH + c];
                a[mi][2] = Qs[r * PITCH + c + 4];
                a[mi][3] = Qs[(r + 8) * PITCH + c + 4];
            }
            #pragma unroll
            for (int ni = 0; ni < 4; ++ni) {
                int n = 32 * wn + ni * 8 + gid;
                float b0 = Ks[n * PITCH + ks * 8 + qid];
                float b1 = Ks[n * PITCH + ks * 8 + qid + 4];
                #pragma unroll
                for (int mi = 0; mi < 2; ++mi)
                    mma8(sacc[mi][ni][0], sacc[mi][ni][1], sacc[mi][ni][2], sacc[mi][ni][3],
                         a[mi][0], a[mi][1], a[mi][2], a[mi][3], b0, b1);
            }
        }
        // write scaled S to smem
        #pragma unroll
        for (int mi = 0; mi < 2; ++mi) {
            int r = 32 * wm + 16 * mi + gid;
            #pragma unroll
            for (int ni = 0; ni < 4; ++ni) {
                int c = 32 * wn + ni * 8 + qid * 2;
                *(float2*)&Ss[r * PITCH + c] =
                    make_float2(sacc[mi][ni][0] * scale, sacc[mi][ni][1] * scale);
                *(float2*)&Ss[(r + 8) * PITCH + c] =
                    make_float2(sacc[mi][ni][2] * scale, sacc[mi][ni][3] * scale);
            }
        }
        __syncthreads();

        // online softmax: 2 threads per row (half rows each)
        {
            int row = tid >> 1, half = tid & 1;
            float4* sr = (float4*)(Ss + row * PITCH + half * 32);
            float mx = -1e30f;
            #pragma unroll
            for (int i = 0; i < 8; ++i) {
                float4 v = sr[i];
                mx = fmaxf(mx, fmaxf(fmaxf(v.x, v.y), fmaxf(v.z, v.w)));
            }
            mx = fmaxf(mx, __shfl_xor_sync(0xffffffffu, mx, 1));
            float mold = mrow[row];
            float mnew = fmaxf(mold, mx);
            float corr = __expf(mold - mnew);
            float psum = 0.f;
            #pragma unroll
            for (int i = 0; i < 8; ++i) {
                float4 v = sr[i];
                v.x = __expf(v.x - mnew); v.y = __expf(v.y - mnew);
                v.z = __expf(v.z - mnew); v.w = __expf(v.w - mnew);
                psum += (v.x + v.y) + (v.z + v.w);
                v.x = tf32r(v.x); v.y = tf32r(v.y); v.z = tf32r(v.z); v.w = tf32r(v.w);
                sr[i] = v;
            }
            psum += __shfl_xor_sync(0xffffffffu, psum, 1);
            if (half == 0) {
                crow[row] = corr;
                mrow[row] = mnew;
                lrow[row] = lrow[row] * corr + psum;
            }
        }
        __syncthreads();

        // rescale O by per-row correction
        #pragma unroll
        for (int mi = 0; mi < 2; ++mi) {
            int r = 32 * wm + 16 * mi + gid;
            float c0 = crow[r], c1 = crow[r + 8];
            #pragma unroll
            for (int ni = 0; ni < 4; ++ni) {
                o[mi][ni][0] *= c0; o[mi][ni][1] *= c0;
                o[mi][ni][2] *= c1; o[mi][ni][3] *= c1;
            }
        }
        // O += P * V (64x64x64)
        #pragma unroll
        for (int ks = 0; ks < 8; ++ks) {
            float a[2][4];
            #pragma unroll
            for (int mi = 0; mi < 2; ++mi) {
                int r = 32 * wm + 16 * mi + gid;
                int c = ks * 8 + qid;
                a[mi][0] = Ss[r * PITCH + c];
                a[mi][1] = Ss[(r + 8) * PITCH + c];
                a[mi][2] = Ss[r * PITCH + c + 4];
                a[mi][3] = Ss[(r + 8) * PITCH + c + 4];
            }
            #pragma unroll
            for (int ni = 0; ni < 4; ++ni) {
                int n = 32 * wn + ni * 8 + gid;
                float b0 = Vs[(ks * 8 + qid) * PITCH + n];
                float b1 = Vs[(ks * 8 + qid + 4) * PITCH + n];
                #pragma unroll
                for (int mi = 0; mi < 2; ++mi)
                    mma8(o[mi][ni][0], o[mi][ni][1], o[mi][ni][2], o[mi][ni][3],
                         a[mi][0], a[mi][1], a[mi][2], a[mi][3], b0, b1);
            }
        }
    }

    // epilogue: normalize and scatter into [b][q][h*64+d]
    const int b = bh >> 3, h = bh & 7;
    #pragma unroll
    for (int mi = 0; mi < 2; ++mi) {
        int r = 32 * wm + 16 * mi + gid;
        float inv0 = 1.0f / lrow[r];
        float inv1 = 1.0f / lrow[r + 8];
        #pragma unroll
        for (int ni = 0; ni < 4; ++ni) {
            int c = 32 * wn + ni * 8 + qid * 2;
            float* d0 = g_AO + (size_t)(b * SEQ + q0 + r) * EMB + h * HD + c;
            float* d1 = g_AO + (size_t)(b * SEQ + q0 + r + 8) * EMB + h * HD + c;
            *(float2*)d0 = make_float2(o[mi][ni][0] * inv0, o[mi][ni][1] * inv0);
            *(float2*)d1 = make_float2(o[mi][ni][2] * inv1, o[mi][ni][3] * inv1);
        }
    }
}

// ---------------------------------------------------------------------------
// Kernel 3: out = AO @ Wo^T + bo   (16384 x 512 x 512), TF32 mma.
// grid: (16384/64, 512/64), block 128
// ---------------------------------------------------------------------------
__global__ __launch_bounds__(128) void out_proj_kernel(
    const float* __restrict__ Wo, const float* __restrict__ bo,
    float* __restrict__ out)
{
    __shared__ float As[64 * PITCH];   // [m][kk]
    __shared__ float Bs[64 * PITCH];   // [kk][n] = Wo[n0+n][k0+kk]
    const int tid  = threadIdx.x;
    const int lane = tid & 31, wid = tid >> 5;
    const int wm = wid >> 1, wn = wid & 1;
    const int gid = lane >> 2, qid = lane & 3;
    const int m0 = blockIdx.x * 64;
    const int n0 = blockIdx.y * 64;

    float o[2][4][4];
    #pragma unroll
    for (int mi = 0; mi < 2; ++mi)
        #pragma unroll
        for (int ni = 0; ni < 4; ++ni)
            #pragma unroll
            for (int t = 0; t < 4; ++t) o[mi][ni][t] = 0.f;

    for (int k0 = 0; k0 < EMB; k0 += 64) {
        __syncthreads();
        #pragma unroll
        for (int i = 0; i < 8; ++i) {
            int g = tid + i * 128;           // 0..1023 float4
            int r = g >> 4, c4 = g & 15;
            float4 a = *(const float4*)(g_AO + (size_t)(m0 + r) * EMB + k0 + c4 * 4);
            a.x = tf32r(a.x); a.y = tf32r(a.y); a.z = tf32r(a.z); a.w = tf32r(a.w);
            ((float4*)As)[r * P4 + c4] = a;
            float4 w = *(const float4*)(Wo + (size_t)(n0 + r) * EMB + k0 + c4 * 4);
            Bs[(c4 * 4 + 0) * PITCH + r] = tf32r(w.x);
            Bs[(c4 * 4 + 1) * PITCH + r] = tf32r(w.y);
            Bs[(c4 * 4 + 2) * PITCH + r] = tf32r(w.z);
            Bs[(c4 * 4 + 3) * PITCH + r] = tf32r(w.w);
        }
        __syncthreads();

        #pragma unroll
        for (int ks = 0; ks < 8; ++ks) {
            float a[2][4];
            #pragma unroll
            for (int mi = 0; mi < 2; ++mi) {
                int r = 32 * wm + 16 * mi + gid;
                int c = ks * 8 + qid;
                a[mi][0] = As[r * PITCH + c];
                a[mi][1] = As[(r + 8) * PITCH + c];
                a[mi][2] = As[r * PITCH + c + 4];
                a[mi][3] = As[(r + 8) * PITCH + c + 4];
            }
            #pragma unroll
            for (int ni = 0; ni < 4; ++ni) {
                int n = 32 * wn + ni * 8 + gid;
                float b0 = Bs[(ks * 8 + qid) * PITCH + n];
                float b1 = Bs[(ks * 8 + qid + 4) * PITCH + n];
                #pragma unroll
                for (int mi = 0; mi < 2; ++mi)
                    mma8(o[mi][ni][0], o[mi][ni][1], o[mi][ni][2], o[mi][ni][3],
                         a[mi][0], a[mi][1], a[mi][2], a[mi][3], b0, b1);
            }
        }
    }

    #pragma unroll
    for (int mi = 0; mi < 2; ++mi) {
        int r = m0 + 32 * wm + 16 * mi + gid;
        #pragma unroll
        for (int ni = 0; ni < 4; ++ni) {
            int c = n0 + 32 * wn + ni * 8 + qid * 2;
            float bb0 = bo[c], bb1 = bo[c + 1];
            *(float2*)(out + (size_t)r * EMB + c) =
                make_float2(o[mi][ni][0] + bb0, o[mi][ni][1] + bb1);
            *(float2*)(out + (size_t)(r + 8) * EMB + c) =
                make_float2(o[mi][ni][2] + bb0, o[mi][ni][3] + bb1);
        }
    }
}

// ---------------------------------------------------------------------------
extern "C" void kernel_launch(void* const* d_in, const int* in_sizes, int n_in,
                              void* d_out, int out_size)
{
    const float* q  = (const float*)d_in[0];
    const float* k  = (const float*)d_in[1];
    const float* v  = (const float*)d_in[2];
    const float* Wq = (const float*)d_in[3];
    const float* Wk = (const float*)d_in[4];
    const float* Wv = (const float*)d_in[5];
    const float* Wo = (const float*)d_in[6];
    const float* bo = (const float*)d_in[7];
    float* out = (float*)d_out;

    const int attn_smem = (4 * 64 * PITCH + 3 * 64) * (int)sizeof(float);  // 70400 B
    cudaFuncSetAttribute(attn_kernel, cudaFuncAttributeMaxDynamicSharedMemorySize,
                         attn_smem);

    proj_kernel<<<dim3(NROWS / 64, 3, 1), 256>>>(q, k, v, Wq, Wk, Wv);
    attn_kernel<<<dim3(SEQ / 64, BH, 1), 128, attn_smem>>>();
    out_proj_kernel<<<dim3((NB * SEQ) / 64, EMB / 64, 1), 128>>>(Wo, bo, out);
}

// round 2
// speedup vs baseline: 2.7367x; 2.7367x over previous
#include <cuda_runtime.h>
#include <cstdint>

// Problem constants
#define NB   8
#define NH   8
#define SEQ  2048
#define HD   64
#define EMB  512
#define BH   (NB * NH)          // 64
#define NROWS (BH * SEQ)        // 131072

#define PITCH 68                // smem pitch (floats)
#define P4    17                // pitch in float4

// Scratch (__device__ globals; allocation-free rule)
static __device__ __align__(256) float g_QP[BH * SEQ * HD];   // [bh][l][f]
static __device__ __align__(256) float g_KP[BH * SEQ * HD];
static __device__ __align__(256) float g_VP[BH * SEQ * HD];
static __device__ __align__(256) float g_AO[NB * SEQ * EMB];  // [b][l][e]

__device__ __forceinline__ float tf32r(float x) {
    uint32_t u;
    asm("cvt.rna.tf32.f32 %0, %1;" : "=r"(u) : "f"(x));
    return __uint_as_float(u);
}

// D += A(16x8,row) * B(8x8,col) ; tf32 inputs (raw fp32 ok: HW truncates), f32 accum
__device__ __forceinline__ void mma8(float& c0, float& c1, float& c2, float& c3,
                                     float a0, float a1, float a2, float a3,
                                     float b0, float b1) {
    asm volatile(
        "mma.sync.aligned.m16n8k8.row.col.f32.tf32.tf32.f32 "
        "{%0,%1,%2,%3}, {%4,%5,%6,%7}, {%8,%9}, {%0,%1,%2,%3};\n"
        : "+f"(c0), "+f"(c1), "+f"(c2), "+f"(c3)
        : "r"(__float_as_uint(a0)), "r"(__float_as_uint(a1)),
          "r"(__float_as_uint(a2)), "r"(__float_as_uint(a3)),
          "r"(__float_as_uint(b0)), "r"(__float_as_uint(b1)));
}

__device__ __forceinline__ void cp16(uint32_t dst, const void* src) {
    asm volatile("cp.async.cg.shared.global [%0], [%1], 16;" :: "r"(dst), "l"(src));
}
__device__ __forceinline__ void cp_commit() {
    asm volatile("cp.async.commit_group;");
}
__device__ __forceinline__ void cp_wait0() {
    asm volatile("cp.async.wait_group 0;");
}

// ---------------------------------------------------------------------------
// Kernel 1: Q/K/V projections as TF32 mma GEMM. out = X(128x64) @ W^T(64x64)
// grid (NROWS/128, 3), block 128 (4 warps, warp tile m32 x n64)
// ---------------------------------------------------------------------------
__global__ __launch_bounds__(128) void proj_kernel(
    const float* __restrict__ Qin, const float* __restrict__ Kin,
    const float* __restrict__ Vin,
    const float* __restrict__ Wq, const float* __restrict__ Wk,
    const float* __restrict__ Wv)
{
    extern __shared__ float sm[];
    float* Xs = sm;                 // 128 x PITCH
    float* Ws = sm + 128 * PITCH;   // 64 x PITCH  (W row-major: Ws[n][k])

    const int tid  = threadIdx.x;
    const int lane = tid & 31, wm = tid >> 5;
    const int gid  = lane >> 2, qid = lane & 3;
    const int which = blockIdx.y;
    const float* W = (which == 0) ? Wq : (which == 1) ? Wk : Wv;
    float* Out     = (which == 0) ? g_QP : (which == 1) ? g_KP : g_VP;
    const int r0 = blockIdx.x * 128;

    // stage W (64x64) rna-rounded
    const float4* W4 = (const float4*)W;
    #pragma unroll
    for (int i = 0; i < 8; ++i) {
        int g = tid + i * 128;                 // 0..1023
        float4 w = W4[g];
        w.x = tf32r(w.x); w.y = tf32r(w.y); w.z = tf32r(w.z); w.w = tf32r(w.w);
        ((float4*)Ws)[(g >> 4) * P4 + (g & 15)] = w;
    }
    // stage X (128x64) rna-rounded
    if (which < 2) {
        const float4* X4 = (const float4*)((which == 0 ? Qin : Kin) + (size_t)r0 * HD);
        #pragma unroll
        for (int i = 0; i < 16; ++i) {
            int g = tid + i * 128;             // 0..2047
            float4 v = X4[g];
            v.x = tf32r(v.x); v.y = tf32r(v.y); v.z = tf32r(v.z); v.w = tf32r(v.w);
            ((float4*)Xs)[(g >> 4) * P4 + (g & 15)] = v;
        }
    } else {
        const int bh = r0 >> 11, l0 = r0 & 2047;
        const int b = bh >> 3, h = bh & 7;
        const float* base = Vin + ((size_t)(b * SEQ + l0)) * EMB + h * HD;
        #pragma unroll
        for (int i = 0; i < 16; ++i) {
            int g = tid + i * 128;
            int r = g >> 4, c4 = g & 15;
            float4 v = *(const float4*)(base + (size_t)r * EMB + c4 * 4);
            v.x = tf32r(v.x); v.y = tf32r(v.y); v.z = tf32r(v.z); v.w = tf32r(v.w);
            ((float4*)Xs)[r * P4 + c4] = v;
        }
    }
    __syncthreads();

    float o[2][8][4];
    #pragma unroll
    for (int mi = 0; mi < 2; ++mi)
        #pragma unroll
        for (int ni = 0; ni < 8; ++ni)
            #pragma unroll
            for (int t = 0; t < 4; ++t) o[mi][ni][t] = 0.f;

    #pragma unroll
    for (int ks = 0; ks < 8; ++ks) {
        float a[2][4];
        #pragma unroll
        for (int mi = 0; mi < 2; ++mi) {
            int r = 32 * wm + 16 * mi + gid;
            int c = ks * 8 + qid;
            a[mi][0] = Xs[r * PITCH + c];
            a[mi][1] = Xs[(r + 8) * PITCH + c];
            a[mi][2] = Xs[r * PITCH + c + 4];
            a[mi][3] = Xs[(r + 8) * PITCH + c + 4];
        }
        #pragma unroll
        for (int ni = 0; ni < 8; ++ni) {
            float b0 = Ws[(ni * 8 + gid) * PITCH + ks * 8 + qid];
            float b1 = Ws[(ni * 8 + gid) * PITCH + ks * 8 + qid + 4];
            #pragma unroll
            for (int mi = 0; mi < 2; ++mi)
                mma8(o[mi][ni][0], o[mi][ni][1], o[mi][ni][2], o[mi][ni][3],
                     a[mi][0], a[mi][1], a[mi][2], a[mi][3], b0, b1);
        }
    }

    #pragma unroll
    for (int mi = 0; mi < 2; ++mi) {
        int r = r0 + 32 * wm + 16 * mi + gid;
        #pragma unroll
        for (int ni = 0; ni < 8; ++ni) {
            int c = ni * 8 + 2 * qid;
            *(float2*)(Out + (size_t)r * HD + c) = make_float2(o[mi][ni][0], o[mi][ni][1]);
            *(float2*)(Out + (size_t)(r + 8) * HD + c) = make_float2(o[mi][ni][2], o[mi][ni][3]);
        }
    }
}

// ---------------------------------------------------------------------------
// Kernel 2: flash attention. Br=128, Bc=64. 4 warps, warp tile m32 x n64.
// Q fragments live in registers; softmax in registers; P warp-private in smem;
// K/V double-buffered via cp.async. One __syncthreads per iteration.
// grid (SEQ/128, BH), block 128, dyn smem 104448 B
// ---------------------------------------------------------------------------
__global__ __launch_bounds__(128, 2) void attn_kernel()
{
    extern __shared__ float sm[];
    float* Ps = sm;                        // 128 x PITCH (Q staging, then P)
    float* KV = sm + 128 * PITCH;          // 2 x (K 64xPITCH + V 64xPITCH)

    const int tid  = threadIdx.x;
    const int lane = tid & 31, wm = tid >> 5;
    const int gid  = lane >> 2, qid = lane & 3;
    const int bh = blockIdx.y;
    const int q0 = blockIdx.x * 128;
    const float scale = 0.044194173824159216f;   // 1/sqrt(512)

    const uint32_t kv_smem = (uint32_t)__cvta_generic_to_shared(KV);

    // prefetch K/V tile 0
    {
        const float4* Kg = (const float4*)(g_KP + (size_t)(bh * SEQ) * HD);
        const float4* Vg = (const float4*)(g_VP + (size_t)(bh * SEQ) * HD);
        #pragma unroll
        for (int i = 0; i < 8; ++i) {
            int g = tid + i * 128;                       // 0..1023
            uint32_t off = (uint32_t)(((g >> 4) * P4 + (g & 15)) * 16);
            cp16(kv_smem + off, Kg + g);
            cp16(kv_smem + (uint32_t)(64 * PITCH * 4) + off, Vg + g);
        }
        cp_commit();
    }

    // stage Q (scaled + rna) into Ps
    {
        const float4* Qg = (const float4*)(g_QP + (size_t)(bh * SEQ + q0) * HD);
        #pragma unroll
        for (int i = 0; i < 16; ++i) {
            int g = tid + i * 128;
            float4 v = Qg[g];
            v.x = tf32r(v.x * scale); v.y = tf32r(v.y * scale);
            v.z = tf32r(v.z * scale); v.w = tf32r(v.w * scale);
            ((float4*)Ps)[(g >> 4) * P4 + (g & 15)] = v;
        }
    }
    __syncthreads();

    // Q fragments -> registers (persist whole kernel)
    float qf[2][8][4];
    #pragma unroll
    for (int mi = 0; mi < 2; ++mi) {
        int r = 32 * wm + 16 * mi + gid;
        #pragma unroll
        for (int ks = 0; ks < 8; ++ks) {
            int c = ks * 8 + qid;
            qf[mi][ks][0] = Ps[r * PITCH + c];
            qf[mi][ks][1] = Ps[(r + 8) * PITCH + c];
            qf[mi][ks][2] = Ps[r * PITCH + c + 4];
            qf[mi][ks][3] = Ps[(r + 8) * PITCH + c + 4];
        }
    }

    float o[2][8][4];
    #pragma unroll
    for (int mi = 0; mi < 2; ++mi)
        #pragma unroll
        for (int ni = 0; ni < 8; ++ni)
            #pragma unroll
            for (int t = 0; t < 4; ++t) o[mi][ni][t] = 0.f;
    float mrow[2][2] = {{-1e30f, -1e30f}, {-1e30f, -1e30f}};
    float lrow[2][2] = {{0.f, 0.f}, {0.f, 0.f}};

    for (int kt = 0; kt < SEQ / 64; ++kt) {
        cp_wait0();
        __syncthreads();   // cur buffer ready; all warps done with prev buffer

        const int cur = kt & 1;
        float* Ks = KV + cur * (2 * 64 * PITCH);
        float* Vs = Ks + 64 * PITCH;

        if (kt + 1 < SEQ / 64) {
            const int nxt = cur ^ 1;
            const float4* Kg = (const float4*)(g_KP + (size_t)(bh * SEQ + (kt + 1) * 64) * HD);
            const float4* Vg = (const float4*)(g_VP + (size_t)(bh * SEQ + (kt + 1) * 64) * HD);
            uint32_t base = kv_smem + (uint32_t)(nxt * 2 * 64 * PITCH * 4);
            #pragma unroll
            for (int i = 0; i < 8; ++i) {
                int g = tid + i * 128;
                uint32_t off = (uint32_t)(((g >> 4) * P4 + (g & 15)) * 16);
                cp16(base + off, Kg + g);
                cp16(base + (uint32_t)(64 * PITCH * 4) + off, Vg + g);
            }
            cp_commit();
        }

        // ---- S = Q K^T (m32 x n64 per warp) ----
        float sacc[2][8][4];
        #pragma unroll
        for (int mi = 0; mi < 2; ++mi)
            #pragma unroll
            for (int ni = 0; ni < 8; ++ni)
                #pragma unroll
                for (int t = 0; t < 4; ++t) sacc[mi][ni][t] = 0.f;

        #pragma unroll
        for (int ks = 0; ks < 8; ++ks) {
            #pragma unroll
            for (int ni = 0; ni < 8; ++ni) {
                float b0 = Ks[(ni * 8 + gid) * PITCH + ks * 8 + qid];
                float b1 = Ks[(ni * 8 + gid) * PITCH + ks * 8 + qid + 4];
                #pragma unroll
                for (int mi = 0; mi < 2; ++mi)
                    mma8(sacc[mi][ni][0], sacc[mi][ni][1], sacc[mi][ni][2], sacc[mi][ni][3],
                         qf[mi][ks][0], qf[mi][ks][1], qf[mi][ks][2], qf[mi][ks][3],
                         b0, b1);
            }
        }

        // ---- online softmax in registers ----
        #pragma unroll
        for (int mi = 0; mi < 2; ++mi) {
            float mx0 = -1e30f, mx1 = -1e30f;
            #pragma unroll
            for (int ni = 0; ni < 8; ++ni) {
                mx0 = fmaxf(mx0, fmaxf(sacc[mi][ni][0], sacc[mi][ni][1]));
                mx1 = fmaxf(mx1, fmaxf(sacc[mi][ni][2], sacc[mi][ni][3]));
            }
            mx0 = fmaxf(mx0, __shfl_xor_sync(0xffffffffu, mx0, 1));
            mx0 = fmaxf(mx0, __shfl_xor_sync(0xffffffffu, mx0, 2));
            mx1 = fmaxf(mx1, __shfl_xor_sync(0xffffffffu, mx1, 1));
            mx1 = fmaxf(mx1, __shfl_xor_sync(0xffffffffu, mx1, 2));

            float mn0 = fmaxf(mrow[mi][0], mx0);
            float mn1 = fmaxf(mrow[mi][1], mx1);
            float c0 = __expf(mrow[mi][0] - mn0);
            float c1 = __expf(mrow[mi][1] - mn1);
            mrow[mi][0] = mn0; mrow[mi][1] = mn1;

            float s0 = 0.f, s1 = 0.f;
            #pragma unroll
            for (int ni = 0; ni < 8; ++ni) {
                sacc[mi][ni][0] = __expf(sacc[mi][ni][0] - mn0);
                sacc[mi][ni][1] = __expf(sacc[mi][ni][1] - mn0);
                sacc[mi][ni][2] = __expf(sacc[mi][ni][2] - mn1);
                sacc[mi][ni][3] = __expf(sacc[mi][ni][3] - mn1);
                s0 += sacc[mi][ni][0] + sacc[mi][ni][1];
                s1 += sacc[mi][ni][2] + sacc[mi][ni][3];
                o[mi][ni][0] *= c0; o[mi][ni][1] *= c0;
                o[mi][ni][2] *= c1; o[mi][ni][3] *= c1;
            }
            s0 += __shfl_xor_sync(0xffffffffu, s0, 1);
            s0 += __shfl_xor_sync(0xffffffffu, s0, 2);
            s1 += __shfl_xor_sync(0xffffffffu, s1, 1);
            s1 += __shfl_xor_sync(0xffffffffu, s1, 2);
            lrow[mi][0] = lrow[mi][0] * c0 + s0;
            lrow[mi][1] = lrow[mi][1] * c1 + s1;
        }

        // ---- write P (warp-private rows) ----
        #pragma unroll
        for (int mi = 0; mi < 2; ++mi) {
            int r = 32 * wm + 16 * mi + gid;
            #pragma unroll
            for (int ni = 0; ni < 8; ++ni) {
                int c = ni * 8 + 2 * qid;
                *(float2*)&Ps[r * PITCH + c] = make_float2(sacc[mi][ni][0], sacc[mi][ni][1]);
                *(float2*)&Ps[(r + 8) * PITCH + c] = make_float2(sacc[mi][ni][2], sacc[mi][ni][3]);
            }
        }
        __syncwarp();

        // ---- O += P V ----
        #pragma unroll
        for (int ks = 0; ks < 8; ++ks) {
            float a[2][4];
            #pragma unroll
            for (int mi = 0; mi < 2; ++mi) {
                int r = 32 * wm + 16 * mi + gid;
                int c = ks * 8 + qid;
                a[mi][0] = Ps[r * PITCH + c];
                a[mi][1] = Ps[(r + 8) * PITCH + c];
                a[mi][2] = Ps[r * PITCH + c + 4];
                a[mi][3] = Ps[(r + 8) * PITCH + c + 4];
            }
            #pragma unroll
            for (int ni = 0; ni < 8; ++ni) {
                float b0 = Vs[(ks * 8 + qid) * PITCH + ni * 8 + gid];
                float b1 = Vs[(ks * 8 + qid + 4) * PITCH + ni * 8 + gid];
                #pragma unroll
                for (int mi = 0; mi < 2; ++mi)
                    mma8(o[mi][ni][0], o[mi][ni][1], o[mi][ni][2], o[mi][ni][3],
                         a[mi][0], a[mi][1], a[mi][2], a[mi][3], b0, b1);
            }
        }
    }

    // epilogue: normalize, scatter to [b][q][h*64+d]
    const int b = bh >> 3, h = bh & 7;
    #pragma unroll
    for (int mi = 0; mi < 2; ++mi) {
        int r = 32 * wm + 16 * mi + gid;
        float inv0 = 1.0f / lrow[mi][0];
        float inv1 = 1.0f / lrow[mi][1];
        #pragma unroll
        for (int ni = 0; ni < 8; ++ni) {
            int c = ni * 8 + 2 * qid;
            float* d0 = g_AO + (size_t)(b * SEQ + q0 + r) * EMB + h * HD + c;
            float* d1 = g_AO + (size_t)(b * SEQ + q0 + r + 8) * EMB + h * HD + c;
            *(float2*)d0 = make_float2(o[mi][ni][0] * inv0, o[mi][ni][1] * inv0);
            *(float2*)d1 = make_float2(o[mi][ni][2] * inv1, o[mi][ni][3] * inv1);
        }
    }
}

// ---------------------------------------------------------------------------
// Kernel 3: out = AO @ Wo^T + bo  (16384 x 512 x 512)
// grid (128, 8), block 128 (4 warps, m32 x n64), k-loop 8
// ---------------------------------------------------------------------------
__global__ __launch_bounds__(128) void out_proj_kernel(
    const float* __restrict__ Wo, const float* __restrict__ bo,
    float* __restrict__ out)
{
    extern __shared__ float sm[];
    float* As = sm;                 // 128 x PITCH
    float* Bs = sm + 128 * PITCH;   // 64 x PITCH  (Bs[n][k] = Wo[n0+n][k0+k])

    const int tid  = threadIdx.x;
    const int lane = tid & 31, wm = tid >> 5;
    const int gid  = lane >> 2, qid = lane & 3;
    const int m0 = blockIdx.x * 128;
    const int n0 = blockIdx.y * 64;

    float o[2][8][4];
    #pragma unroll
    for (int mi = 0; mi < 2; ++mi)
        #pragma unroll
        for (int ni = 0; ni < 8; ++ni)
            #pragma unroll
            for (int t = 0; t < 4; ++t) o[mi][ni][t] = 0.f;

    for (int k0 = 0; k0 < EMB; k0 += 64) {
        __syncthreads();
        #pragma unroll
        for (int i = 0; i < 16; ++i) {
            int g = tid + i * 128;             // 0..2047
            int r = g >> 4, c4 = g & 15;
            float4 a = *(const float4*)(g_AO + (size_t)(m0 + r) * EMB + k0 + c4 * 4);
            a.x = tf32r(a.x); a.y = tf32r(a.y); a.z = tf32r(a.z); a.w = tf32r(a.w);
            ((float4*)As)[r * P4 + c4] = a;
        }
        #pragma unroll
        for (int i = 0; i < 8; ++i) {
            int g = tid + i * 128;             // 0..1023
            int r = g >> 4, c4 = g & 15;
            float4 w = *(const float4*)(Wo + (size_t)(n0 + r) * EMB + k0 + c4 * 4);
            w.x = tf32r(w.x); w.y = tf32r(w.y); w.z = tf32r(w.z); w.w = tf32r(w.w);
            ((float4*)Bs)[r * P4 + c4] = w;
        }
        __syncthreads();

        #pragma unroll
        for (int ks = 0; ks < 8; ++ks) {
            float a[2][4];
            #pragma unroll
            for (int mi = 0; mi < 2; ++mi) {
                int r = 32 * wm + 16 * mi + gid;
                int c = ks * 8 + qid;
                a[mi][0] = As[r * PITCH + c];
                a[mi][1] = As[(r + 8) * PITCH + c];
                a[mi][2] = As[r * PITCH + c + 4];
                a[mi][3] = As[(r + 8) * PITCH + c + 4];
            }
            #pragma unroll
            for (int ni = 0; ni < 8; ++ni) {
                float b0 = Bs[(ni * 8 + gid) * PITCH + ks * 8 + qid];
                float b1 = Bs[(ni * 8 + gid) * PITCH + ks * 8 + qid + 4];
                #pragma unroll
                for (int mi = 0; mi < 2; ++mi)
                    mma8(o[mi][ni][0], o[mi][ni][1], o[mi][ni][2], o[mi][ni][3],
                         a[mi][0], a[mi][1], a[mi][2], a[mi][3], b0, b1);
            }
        }
    }

    #pragma unroll
    for (int mi = 0; mi < 2; ++mi) {
        int r = m0 + 32 * wm + 16 * mi + gid;
        #pragma unroll
        for (int ni = 0; ni < 8; ++ni) {
            int c = n0 + ni * 8 + 2 * qid;
            float bb0 = bo[c], bb1 = bo[c + 1];
            *(float2*)(out + (size_t)r * EMB + c) =
                make_float2(o[mi][ni][0] + bb0, o[mi][ni][1] + bb1);
            *(float2*)(out + (size_t)(r + 8) * EMB + c) =
                make_float2(o[mi][ni][2] + bb0, o[mi][ni][3] + bb1);
        }
    }
}

// ---------------------------------------------------------------------------
extern "C" void kernel_launch(void* const* d_in, const int* in_sizes, int n_in,
                              void* d_out, int out_size)
{
    const float* q  = (const float*)d_in[0];
    const float* k  = (const float*)d_in[1];
    const float* v  = (const float*)d_in[2];
    const float* Wq = (const float*)d_in[3];
    const float* Wk = (const float*)d_in[4];
    const float* Wv = (const float*)d_in[5];
    const float* Wo = (const float*)d_in[6];
    const float* bo = (const float*)d_in[7];
    float* out = (float*)d_out;

    const int proj_smem = (128 * PITCH + 64 * PITCH) * (int)sizeof(float);   // 52224
    const int attn_smem = (128 * PITCH + 4 * 64 * PITCH) * (int)sizeof(float); // 104448
    const int oproj_smem = proj_smem;

    static bool attr_done = false;
    if (!attr_done) {
        cudaFuncSetAttribute(proj_kernel, cudaFuncAttributeMaxDynamicSharedMemorySize, proj_smem);
        cudaFuncSetAttribute(attn_kernel, cudaFuncAttributeMaxDynamicSharedMemorySize, attn_smem);
        cudaFuncSetAttribute(out_proj_kernel, cudaFuncAttributeMaxDynamicSharedMemorySize, oproj_smem);
        attr_done = true;
    }

    proj_kernel<<<dim3(NROWS / 128, 3, 1), 128, proj_smem>>>(q, k, v, Wq, Wk, Wv);
    attn_kernel<<<dim3(SEQ / 128, BH, 1), 128, attn_smem>>>();
    out_proj_kernel<<<dim3((NB * SEQ) / 128, EMB / 64, 1), 128, oproj_smem>>>(Wo, bo, out);
}

// round 3
// speedup vs baseline: 4.9190x; 1.7975x over previous
#include <cuda_runtime.h>
#include <cuda_fp16.h>
#include <cstdint>

// Problem constants
#define NB   8
#define NH   8
#define SEQ  2048
#define HD   64
#define EMB  512
#define BH   (NB * NH)          // 64
#define NROWS (BH * SEQ)        // 131072

#define PITCH 68                // fp32 smem pitch (proj kernel)
#define P4    17
#define PH    72                // half smem pitch (72 halves = 144 B = 9 x 16B)

// Scratch (__device__ globals)
static __device__ __align__(256) __half g_QPh[BH * SEQ * HD];  // [bh][l][d], pre-scaled
static __device__ __align__(256) __half g_KPh[BH * SEQ * HD];  // [bh][l][d]
static __device__ __align__(256) __half g_VPt[BH * HD * SEQ];  // [bh][d][l]  (transposed!)
static __device__ __align__(256) __half g_AOh[NB * SEQ * EMB]; // [b][l][e]

__device__ __forceinline__ float tf32r(float x) {
    uint32_t u;
    asm("cvt.rna.tf32.f32 %0, %1;" : "=r"(u) : "f"(x));
    return __uint_as_float(u);
}
__device__ __forceinline__ uint32_t f22h(float lo, float hi) {
    __half2 h = __floats2half2_rn(lo, hi);
    return *reinterpret_cast<uint32_t*>(&h);
}

// tf32 mma (proj kernel only)
__device__ __forceinline__ void mma8(float& c0, float& c1, float& c2, float& c3,
                                     float a0, float a1, float a2, float a3,
                                     float b0, float b1) {
    asm volatile(
        "mma.sync.aligned.m16n8k8.row.col.f32.tf32.tf32.f32 "
        "{%0,%1,%2,%3}, {%4,%5,%6,%7}, {%8,%9}, {%0,%1,%2,%3};\n"
        : "+f"(c0), "+f"(c1), "+f"(c2), "+f"(c3)
        : "r"(__float_as_uint(a0)), "r"(__float_as_uint(a1)),
          "r"(__float_as_uint(a2)), "r"(__float_as_uint(a3)),
          "r"(__float_as_uint(b0)), "r"(__float_as_uint(b1)));
}
// fp16 mma, f32 accum
__device__ __forceinline__ void mma16(float& c0, float& c1, float& c2, float& c3,
                                      uint32_t a0, uint32_t a1, uint32_t a2, uint32_t a3,
                                      uint32_t b0, uint32_t b1) {
    asm volatile(
        "mma.sync.aligned.m16n8k16.row.col.f32.f16.f16.f32 "
        "{%0,%1,%2,%3}, {%4,%5,%6,%7}, {%8,%9}, {%0,%1,%2,%3};\n"
        : "+f"(c0), "+f"(c1), "+f"(c2), "+f"(c3)
        : "r"(a0), "r"(a1), "r"(a2), "r"(a3), "r"(b0), "r"(b1));
}

__device__ __forceinline__ void cp16(uint32_t dst, const void* src) {
    asm volatile("cp.async.cg.shared.global [%0], [%1], 16;" :: "r"(dst), "l"(src));
}
__device__ __forceinline__ void cp_commit() { asm volatile("cp.async.commit_group;"); }
__device__ __forceinline__ void cp_wait0()  { asm volatile("cp.async.wait_group 0;"); }

// ---------------------------------------------------------------------------
// Kernel 1: projections (tf32 mma), epilogue converts to half.
//   which 0: Q (x scale) -> g_QPh ; 1: K -> g_KPh ; 2: V -> g_VPt (transposed)
// grid (NROWS/128, 3), block 128
// ---------------------------------------------------------------------------
__global__ __launch_bounds__(128) void proj_kernel(
    const float* __restrict__ Qin, const float* __restrict__ Kin,
    const float* __restrict__ Vin,
    const float* __restrict__ Wq, const float* __restrict__ Wk,
    const float* __restrict__ Wv)
{
    extern __shared__ float sm[];
    float* Xs = sm;                 // 128 x PITCH
    float* Ws = sm + 128 * PITCH;   // 64 x PITCH

    const int tid  = threadIdx.x;
    const int lane = tid & 31, wm = tid >> 5;
    const int gid  = lane >> 2, qid = lane & 3;
    const int which = blockIdx.y;
    const float* W = (which == 0) ? Wq : (which == 1) ? Wk : Wv;
    const int r0 = blockIdx.x * 128;

    const float4* W4 = (const float4*)W;
    #pragma unroll
    for (int i = 0; i < 8; ++i) {
        int g = tid + i * 128;
        float4 w = W4[g];
        w.x = tf32r(w.x); w.y = tf32r(w.y); w.z = tf32r(w.z); w.w = tf32r(w.w);
        ((float4*)Ws)[(g >> 4) * P4 + (g & 15)] = w;
    }
    if (which < 2) {
        const float4* X4 = (const float4*)((which == 0 ? Qin : Kin) + (size_t)r0 * HD);
        #pragma unroll
        for (int i = 0; i < 16; ++i) {
            int g = tid + i * 128;
            float4 v = X4[g];
            v.x = tf32r(v.x); v.y = tf32r(v.y); v.z = tf32r(v.z); v.w = tf32r(v.w);
            ((float4*)Xs)[(g >> 4) * P4 + (g & 15)] = v;
        }
    } else {
        const int bh = r0 >> 11, l0 = r0 & 2047;
        const int b = bh >> 3, h = bh & 7;
        const float* base = Vin + ((size_t)(b * SEQ + l0)) * EMB + h * HD;
        #pragma unroll
        for (int i = 0; i < 16; ++i) {
            int g = tid + i * 128;
            int r = g >> 4, c4 = g & 15;
            float4 v = *(const float4*)(base + (size_t)r * EMB + c4 * 4);
            v.x = tf32r(v.x); v.y = tf32r(v.y); v.z = tf32r(v.z); v.w = tf32r(v.w);
            ((float4*)Xs)[r * P4 + c4] = v;
        }
    }
    __syncthreads();

    float o[2][8][4];
    #pragma unroll
    for (int mi = 0; mi < 2; ++mi)
        #pragma unroll
        for (int ni = 0; ni < 8; ++ni)
            #pragma unroll
            for (int t = 0; t < 4; ++t) o[mi][ni][t] = 0.f;

    #pragma unroll
    for (int ks = 0; ks < 8; ++ks) {
        float a[2][4];
        #pragma unroll
        for (int mi = 0; mi < 2; ++mi) {
            int r = 32 * wm + 16 * mi + gid;
            int c = ks * 8 + qid;
            a[mi][0] = Xs[r * PITCH + c];
            a[mi][1] = Xs[(r + 8) * PITCH + c];
            a[mi][2] = Xs[r * PITCH + c + 4];
            a[mi][3] = Xs[(r + 8) * PITCH + c + 4];
        }
        #pragma unroll
        for (int ni = 0; ni < 8; ++ni) {
            float b0 = Ws[(ni * 8 + gid) * PITCH + ks * 8 + qid];
            float b1 = Ws[(ni * 8 + gid) * PITCH + ks * 8 + qid + 4];
            #pragma unroll
            for (int mi = 0; mi < 2; ++mi)
                mma8(o[mi][ni][0], o[mi][ni][1], o[mi][ni][2], o[mi][ni][3],
                     a[mi][0], a[mi][1], a[mi][2], a[mi][3], b0, b1);
        }
    }

    const float qscale = 0.044194173824159216f;   // 1/sqrt(512)
    if (which == 0) {
        #pragma unroll
        for (int mi = 0; mi < 2; ++mi) {
            int r = r0 + 32 * wm + 16 * mi + gid;
            #pragma unroll
            for (int ni = 0; ni < 8; ++ni) {
                int c = ni * 8 + 2 * qid;
                *(uint32_t*)(g_QPh + (size_t)r * HD + c) =
                    f22h(o[mi][ni][0] * qscale, o[mi][ni][1] * qscale);
                *(uint32_t*)(g_QPh + (size_t)(r + 8) * HD + c) =
                    f22h(o[mi][ni][2] * qscale, o[mi][ni][3] * qscale);
            }
        }
    } else if (which == 1) {
        #pragma unroll
        for (int mi = 0; mi < 2; ++mi) {
            int r = r0 + 32 * wm + 16 * mi + gid;
            #pragma unroll
            for (int ni = 0; ni < 8; ++ni) {
                int c = ni * 8 + 2 * qid;
                *(uint32_t*)(g_KPh + (size_t)r * HD + c) = f22h(o[mi][ni][0], o[mi][ni][1]);
                *(uint32_t*)(g_KPh + (size_t)(r + 8) * HD + c) = f22h(o[mi][ni][2], o[mi][ni][3]);
            }
        }
    } else {
        // transposed store: g_VPt[bh][d][l]
        const int bh = r0 >> 11;
        const size_t base = (size_t)bh * HD * SEQ;
        const int l0 = (r0 & 2047);
        #pragma unroll
        for (int mi = 0; mi < 2; ++mi) {
            int l = l0 + 32 * wm + 16 * mi + gid;
            #pragma unroll
            for (int ni = 0; ni < 8; ++ni) {
                int c = ni * 8 + 2 * qid;
                g_VPt[base + (size_t)c * SEQ + l]           = __float2half_rn(o[mi][ni][0]);
                g_VPt[base + (size_t)(c + 1) * SEQ + l]     = __float2half_rn(o[mi][ni][1]);
                g_VPt[base + (size_t)c * SEQ + l + 8]       = __float2half_rn(o[mi][ni][2]);
                g_VPt[base + (size_t)(c + 1) * SEQ + l + 8] = __float2half_rn(o[mi][ni][3]);
            }
        }
    }
}

// ---------------------------------------------------------------------------
// Kernel 2: fp16 flash attention. Br=128, Bc=64. 4 warps, warp tile m32 x n64.
// Q and P live entirely in registers (FA2 C->A fragment identity).
// grid (SEQ/128, BH), block 128, dyn smem 55296 B
// ---------------------------------------------------------------------------
__global__ __launch_bounds__(128, 2) void attn_kernel()
{
    extern __shared__ __align__(16) unsigned char smraw[];
    __half* Qs = (__half*)smraw;                    // 128 x PH
    __half* KV = (__half*)(smraw + 128 * PH * 2);   // 2 buffers x (K 64xPH + V 64xPH)

    const int tid  = threadIdx.x;
    const int lane = tid & 31, wm = tid >> 5;
    const int gid  = lane >> 2, qid = lane & 3;
    const int bh = blockIdx.y;
    const int q0 = blockIdx.x * 128;

    const uint32_t kv_smem = (uint32_t)__cvta_generic_to_shared(KV);
    const int TILE_H = 64 * PH;          // halves per tile
    const int TILE_B = TILE_H * 2;       // bytes per tile (9216)

    // prefetch K/V tile 0 (half rows: 64 rows x 128B)
    {
        const __half* Kg = g_KPh + (size_t)bh * SEQ * HD;
        const __half* Vg = g_VPt + (size_t)bh * HD * SEQ;
        #pragma unroll
        for (int i = 0; i < 4; ++i) {
            int g = tid + i * 128;                   // 0..511
            int row = g >> 3, c8 = g & 7;
            uint32_t off = (uint32_t)(row * 144 + c8 * 16);
            cp16(kv_smem + off, Kg + (size_t)row * HD + c8 * 8);
            cp16(kv_smem + (uint32_t)TILE_B + off, Vg + (size_t)row * SEQ + c8 * 8);
        }
        cp_commit();
    }

    // stage Q (already scaled, half)
    {
        const __half* Qg = g_QPh + (size_t)(bh * SEQ + q0) * HD;
        #pragma unroll
        for (int i = 0; i < 8; ++i) {
            int g = tid + i * 128;                   // 0..1023 groups of 8 halves
            int row = g >> 3, c8 = g & 7;
            *(float4*)(Qs + row * PH + c8 * 8) = *(const float4*)(Qg + (size_t)row * HD + c8 * 8);
        }
    }
    __syncthreads();

    // Q fragments -> registers (A layout m16n8k16), persist whole kernel
    uint32_t qf[2][4][4];
    #pragma unroll
    for (int mi = 0; mi < 2; ++mi) {
        int r = 32 * wm + 16 * mi + gid;
        #pragma unroll
        for (int kt = 0; kt < 4; ++kt) {
            int c = kt * 16 + 2 * qid;
            qf[mi][kt][0] = *(uint32_t*)&Qs[r * PH + c];
            qf[mi][kt][1] = *(uint32_t*)&Qs[(r + 8) * PH + c];
            qf[mi][kt][2] = *(uint32_t*)&Qs[r * PH + c + 8];
            qf[mi][kt][3] = *(uint32_t*)&Qs[(r + 8) * PH + c + 8];
        }
    }

    float o[2][8][4];
    #pragma unroll
    for (int mi = 0; mi < 2; ++mi)
        #pragma unroll
        for (int ni = 0; ni < 8; ++ni)
            #pragma unroll
            for (int t = 0; t < 4; ++t) o[mi][ni][t] = 0.f;
    float mrow[2][2] = {{-1e30f, -1e30f}, {-1e30f, -1e30f}};
    float lrow[2][2] = {{0.f, 0.f}, {0.f, 0.f}};

    for (int kt64 = 0; kt64 < SEQ / 64; ++kt64) {
        cp_wait0();
        __syncthreads();

        const int cur = kt64 & 1;
        __half* Ks = KV + cur * (2 * TILE_H);
        __half* Vs = Ks + TILE_H;

        if (kt64 + 1 < SEQ / 64) {
            const int nxt = cur ^ 1;
            const __half* Kg = g_KPh + (size_t)(bh * SEQ + (kt64 + 1) * 64) * HD;
            const __half* Vg = g_VPt + (size_t)bh * HD * SEQ + (kt64 + 1) * 64;
            uint32_t base = kv_smem + (uint32_t)(nxt * 2 * TILE_B);
            #pragma unroll
            for (int i = 0; i < 4; ++i) {
                int g = tid + i * 128;
                int row = g >> 3, c8 = g & 7;
                uint32_t off = (uint32_t)(row * 144 + c8 * 16);
                cp16(base + off, Kg + (size_t)row * HD + c8 * 8);
                cp16(base + (uint32_t)TILE_B + off, Vg + (size_t)row * SEQ + c8 * 8);
            }
            cp_commit();
        }

        // ---- S = Q K^T ----
        float sacc[2][8][4];
        #pragma unroll
        for (int mi = 0; mi < 2; ++mi)
            #pragma unroll
            for (int ni = 0; ni < 8; ++ni)
                #pragma unroll
                for (int t = 0; t < 4; ++t) sacc[mi][ni][t] = 0.f;

        #pragma unroll
        for (int kt = 0; kt < 4; ++kt) {
            #pragma unroll
            for (int ni = 0; ni < 8; ++ni) {
                uint32_t b0 = *(uint32_t*)&Ks[(ni * 8 + gid) * PH + kt * 16 + 2 * qid];
                uint32_t b1 = *(uint32_t*)&Ks[(ni * 8 + gid) * PH + kt * 16 + 2 * qid + 8];
                #pragma unroll
                for (int mi = 0; mi < 2; ++mi)
                    mma16(sacc[mi][ni][0], sacc[mi][ni][1], sacc[mi][ni][2], sacc[mi][ni][3],
                          qf[mi][kt][0], qf[mi][kt][1], qf[mi][kt][2], qf[mi][kt][3],
                          b0, b1);
            }
        }

        // ---- online softmax (registers) ----
        #pragma unroll
        for (int mi = 0; mi < 2; ++mi) {
            float mx0 = -1e30f, mx1 = -1e30f;
            #pragma unroll
            for (int ni = 0; ni < 8; ++ni) {
                mx0 = fmaxf(mx0, fmaxf(sacc[mi][ni][0], sacc[mi][ni][1]));
                mx1 = fmaxf(mx1, fmaxf(sacc[mi][ni][2], sacc[mi][ni][3]));
            }
            mx0 = fmaxf(mx0, __shfl_xor_sync(0xffffffffu, mx0, 1));
            mx0 = fmaxf(mx0, __shfl_xor_sync(0xffffffffu, mx0, 2));
            mx1 = fmaxf(mx1, __shfl_xor_sync(0xffffffffu, mx1, 1));
            mx1 = fmaxf(mx1, __shfl_xor_sync(0xffffffffu, mx1, 2));

            float mn0 = fmaxf(mrow[mi][0], mx0);
            float mn1 = fmaxf(mrow[mi][1], mx1);
            float c0 = __expf(mrow[mi][0] - mn0);
            float c1 = __expf(mrow[mi][1] - mn1);
            mrow[mi][0] = mn0; mrow[mi][1] = mn1;

            float s0 = 0.f, s1 = 0.f;
            #pragma unroll
            for (int ni = 0; ni < 8; ++ni) {
                sacc[mi][ni][0] = __expf(sacc[mi][ni][0] - mn0);
                sacc[mi][ni][1] = __expf(sacc[mi][ni][1] - mn0);
                sacc[mi][ni][2] = __expf(sacc[mi][ni][2] - mn1);
                sacc[mi][ni][3] = __expf(sacc[mi][ni][3] - mn1);
                s0 += sacc[mi][ni][0] + sacc[mi][ni][1];
                s1 += sacc[mi][ni][2] + sacc[mi][ni][3];
                o[mi][ni][0] *= c0; o[mi][ni][1] *= c0;
                o[mi][ni][2] *= c1; o[mi][ni][3] *= c1;
            }
            s0 += __shfl_xor_sync(0xffffffffu, s0, 1);
            s0 += __shfl_xor_sync(0xffffffffu, s0, 2);
            s1 += __shfl_xor_sync(0xffffffffu, s1, 1);
            s1 += __shfl_xor_sync(0xffffffffu, s1, 2);
            lrow[mi][0] = lrow[mi][0] * c0 + s0;
            lrow[mi][1] = lrow[mi][1] * c1 + s1;
        }

        // ---- O += P V : P packed in registers (C layout == A layout) ----
        #pragma unroll
        for (int kt = 0; kt < 4; ++kt) {
            uint32_t pf[2][4];
            #pragma unroll
            for (int mi = 0; mi < 2; ++mi) {
                pf[mi][0] = f22h(sacc[mi][2 * kt][0],     sacc[mi][2 * kt][1]);
                pf[mi][1] = f22h(sacc[mi][2 * kt][2],     sacc[mi][2 * kt][3]);
                pf[mi][2] = f22h(sacc[mi][2 * kt + 1][0], sacc[mi][2 * kt + 1][1]);
                pf[mi][3] = f22h(sacc[mi][2 * kt + 1][2], sacc[mi][2 * kt + 1][3]);
            }
            #pragma unroll
            for (int ni = 0; ni < 8; ++ni) {
                uint32_t b0 = *(uint32_t*)&Vs[(ni * 8 + gid) * PH + kt * 16 + 2 * qid];
                uint32_t b1 = *(uint32_t*)&Vs[(ni * 8 + gid) * PH + kt * 16 + 2 * qid + 8];
                #pragma unroll
                for (int mi = 0; mi < 2; ++mi)
                    mma16(o[mi][ni][0], o[mi][ni][1], o[mi][ni][2], o[mi][ni][3],
                          pf[mi][0], pf[mi][1], pf[mi][2], pf[mi][3], b0, b1);
            }
        }
    }

    // epilogue: normalize, store half to g_AOh[b][q][h*64+d]
    const int b = bh >> 3, hh = bh & 7;
    #pragma unroll
    for (int mi = 0; mi < 2; ++mi) {
        int r = 32 * wm + 16 * mi + gid;
        float inv0 = 1.0f / lrow[mi][0];
        float inv1 = 1.0f / lrow[mi][1];
        #pragma unroll
        for (int ni = 0; ni < 8; ++ni) {
            int c = ni * 8 + 2 * qid;
            *(uint32_t*)(g_AOh + (size_t)(b * SEQ + q0 + r) * EMB + hh * HD + c) =
                f22h(o[mi][ni][0] * inv0, o[mi][ni][1] * inv0);
            *(uint32_t*)(g_AOh + (size_t)(b * SEQ + q0 + r + 8) * EMB + hh * HD + c) =
                f22h(o[mi][ni][2] * inv1, o[mi][ni][3] * inv1);
        }
    }
}

// ---------------------------------------------------------------------------
// Kernel 3: out = AOh @ Wo^T + bo  (16384 x 512 x 512), fp16 mma.
// grid (128, 8), block 128
// ---------------------------------------------------------------------------
__global__ __launch_bounds__(128) void out_proj_kernel(
    const float* __restrict__ Wo, const float* __restrict__ bo,
    float* __restrict__ out)
{
    extern __shared__ __align__(16) unsigned char smraw[];
    __half* As = (__half*)smraw;                    // 128 x PH
    __half* Bs = (__half*)(smraw + 128 * PH * 2);   // 64 x PH  (Bs[n][k] = Wo[n0+n][k0+k])

    const int tid  = threadIdx.x;
    const int lane = tid & 31, wm = tid >> 5;
    const int gid  = lane >> 2, qid = lane & 3;
    const int m0 = blockIdx.x * 128;
    const int n0 = blockIdx.y * 64;

    float o[2][8][4];
    #pragma unroll
    for (int mi = 0; mi < 2; ++mi)
        #pragma unroll
        for (int ni = 0; ni < 8; ++ni)
            #pragma unroll
            for (int t = 0; t < 4; ++t) o[mi][ni][t] = 0.f;

    for (int k0 = 0; k0 < EMB; k0 += 64) {
        __syncthreads();
        #pragma unroll
        for (int i = 0; i < 8; ++i) {
            int g = tid + i * 128;                   // 0..1023 groups of 8 halves
            int row = g >> 3, c8 = g & 7;
            *(float4*)(As + row * PH + c8 * 8) =
                *(const float4*)(g_AOh + (size_t)(m0 + row) * EMB + k0 + c8 * 8);
        }
        #pragma unroll
        for (int i = 0; i < 4; ++i) {
            int g = tid + i * 128;                   // 0..511
            int row = g >> 3, c8 = g & 7;
            const float* wp = Wo + (size_t)(n0 + row) * EMB + k0 + c8 * 8;
            float4 w0 = *(const float4*)wp;
            float4 w1 = *(const float4*)(wp + 4);
            uint4 pw;
            pw.x = f22h(w0.x, w0.y); pw.y = f22h(w0.z, w0.w);
            pw.z = f22h(w1.x, w1.y); pw.w = f22h(w1.z, w1.w);
            *(uint4*)(Bs + row * PH + c8 * 8) = pw;
        }
        __syncthreads();

        #pragma unroll
        for (int kt = 0; kt < 4; ++kt) {
            uint32_t a[2][4];
            #pragma unroll
            for (int mi = 0; mi < 2; ++mi) {
                int r = 32 * wm + 16 * mi + gid;
                int c = kt * 16 + 2 * qid;
                a[mi][0] = *(uint32_t*)&As[r * PH + c];
                a[mi][1] = *(uint32_t*)&As[(r + 8) * PH + c];
                a[mi][2] = *(uint32_t*)&As[r * PH + c + 8];
                a[mi][3] = *(uint32_t*)&As[(r + 8) * PH + c + 8];
            }
            #pragma unroll
            for (int ni = 0; ni < 8; ++ni) {
                uint32_t b0 = *(uint32_t*)&Bs[(ni * 8 + gid) * PH + kt * 16 + 2 * qid];
                uint32_t b1 = *(uint32_t*)&Bs[(ni * 8 + gid) * PH + kt * 16 + 2 * qid + 8];
                #pragma unroll
                for (int mi = 0; mi < 2; ++mi)
                    mma16(o[mi][ni][0], o[mi][ni][1], o[mi][ni][2], o[mi][ni][3],
                          a[mi][0], a[mi][1], a[mi][2], a[mi][3], b0, b1);
            }
        }
    }

    #pragma unroll
    for (int mi = 0; mi < 2; ++mi) {
        int r = m0 + 32 * wm + 16 * mi + gid;
        #pragma unroll
        for (int ni = 0; ni < 8; ++ni) {
            int c = n0 + ni * 8 + 2 * qid;
            float bb0 = bo[c], bb1 = bo[c + 1];
            *(float2*)(out + (size_t)r * EMB + c) =
                make_float2(o[mi][ni][0] + bb0, o[mi][ni][1] + bb1);
            *(float2*)(out + (size_t)(r + 8) * EMB + c) =
                make_float2(o[mi][ni][2] + bb0, o[mi][ni][3] + bb1);
        }
    }
}

// ---------------------------------------------------------------------------
extern "C" void kernel_launch(void* const* d_in, const int* in_sizes, int n_in,
                              void* d_out, int out_size)
{
    const float* q  = (const float*)d_in[0];
    const float* k  = (const float*)d_in[1];
    const float* v  = (const float*)d_in[2];
    const float* Wq = (const float*)d_in[3];
    const float* Wk = (const float*)d_in[4];
    const float* Wv = (const float*)d_in[5];
    const float* Wo = (const float*)d_in[6];
    const float* bo = (const float*)d_in[7];
    float* out = (float*)d_out;

    const int proj_smem  = (128 * PITCH + 64 * PITCH) * (int)sizeof(float);       // 52224
    const int attn_smem  = (128 * PH + 4 * 64 * PH) * (int)sizeof(__half);        // 55296
    const int oproj_smem = (128 * PH + 64 * PH) * (int)sizeof(__half);            // 27648

    cudaFuncSetAttribute(proj_kernel, cudaFuncAttributeMaxDynamicSharedMemorySize, proj_smem);
    cudaFuncSetAttribute(attn_kernel, cudaFuncAttributeMaxDynamicSharedMemorySize, attn_smem);
    cudaFuncSetAttribute(out_proj_kernel, cudaFuncAttributeMaxDynamicSharedMemorySize, oproj_smem);

    proj_kernel<<<dim3(NROWS / 128, 3, 1), 128, proj_smem>>>(q, k, v, Wq, Wk, Wv);
    attn_kernel<<<dim3(SEQ / 128, BH, 1), 128, attn_smem>>>();
    out_proj_kernel<<<dim3((NB * SEQ) / 128, EMB / 64, 1), 128, oproj_smem>>>(Wo, bo, out);
}

// round 4
// speedup vs baseline: 5.4539x; 1.1087x over previous
#include <cuda_runtime.h>
#include <cuda_fp16.h>
#include <cstdint>

// Problem constants
#define NB   8
#define NH   8
#define SEQ  2048
#define HD   64
#define EMB  512
#define BH   (NB * NH)          // 64
#define NROWS (BH * SEQ)        // 131072

#define PITCH 68                // fp32 smem pitch (proj kernel)
#define P4    17
#define PH    72                // half smem pitch (72 halves = 144 B)

// Scratch (__device__ globals)
static __device__ __align__(256) __half g_QPh[BH * SEQ * HD];  // [bh][l][d], pre-scaled by 1/sqrt(512)*log2(e)
static __device__ __align__(256) __half g_KPh[BH * SEQ * HD];  // [bh][l][d]
static __device__ __align__(256) __half g_VPt[BH * HD * SEQ];  // [bh][d][l]  (transposed)
static __device__ __align__(256) __half g_AOh[NB * SEQ * EMB]; // [b][l][e]
static __device__ __align__(256) __half g_Woh[EMB * EMB];      // Wo as half

__device__ __forceinline__ float tf32r(float x) {
    uint32_t u;
    asm("cvt.rna.tf32.f32 %0, %1;" : "=r"(u) : "f"(x));
    return __uint_as_float(u);
}
__device__ __forceinline__ uint32_t f22h(float lo, float hi) {
    __half2 h = __floats2half2_rn(lo, hi);
    return *reinterpret_cast<uint32_t*>(&h);
}

// tf32 mma (proj only)
__device__ __forceinline__ void mma8(float& c0, float& c1, float& c2, float& c3,
                                     float a0, float a1, float a2, float a3,
                                     float b0, float b1) {
    asm volatile(
        "mma.sync.aligned.m16n8k8.row.col.f32.tf32.tf32.f32 "
        "{%0,%1,%2,%3}, {%4,%5,%6,%7}, {%8,%9}, {%0,%1,%2,%3};\n"
        : "+f"(c0), "+f"(c1), "+f"(c2), "+f"(c3)
        : "r"(__float_as_uint(a0)), "r"(__float_as_uint(a1)),
          "r"(__float_as_uint(a2)), "r"(__float_as_uint(a3)),
          "r"(__float_as_uint(b0)), "r"(__float_as_uint(b1)));
}
// fp16 mma, f32 accum
__device__ __forceinline__ void mma16(float& c0, float& c1, float& c2, float& c3,
                                      uint32_t a0, uint32_t a1, uint32_t a2, uint32_t a3,
                                      uint32_t b0, uint32_t b1) {
    asm volatile(
        "mma.sync.aligned.m16n8k16.row.col.f32.f16.f16.f32 "
        "{%0,%1,%2,%3}, {%4,%5,%6,%7}, {%8,%9}, {%0,%1,%2,%3};\n"
        : "+f"(c0), "+f"(c1), "+f"(c2), "+f"(c3)
        : "r"(a0), "r"(a1), "r"(a2), "r"(a3), "r"(b0), "r"(b1));
}

__device__ __forceinline__ void ldsm4(uint32_t& r0, uint32_t& r1, uint32_t& r2, uint32_t& r3,
                                      uint32_t a) {
    asm volatile("ldmatrix.sync.aligned.m8n8.x4.shared.b16 {%0,%1,%2,%3}, [%4];"
                 : "=r"(r0), "=r"(r1), "=r"(r2), "=r"(r3) : "r"(a));
}

__device__ __forceinline__ void cp16(uint32_t dst, const void* src) {
    asm volatile("cp.async.cg.shared.global [%0], [%1], 16;" :: "r"(dst), "l"(src));
}
__device__ __forceinline__ void cp_commit() { asm volatile("cp.async.commit_group;"); }
__device__ __forceinline__ void cp_wait0()  { asm volatile("cp.async.wait_group 0;"); }
__device__ __forceinline__ void cp_wait1()  { asm volatile("cp.async.wait_group 1;"); }

// ---------------------------------------------------------------------------
// Kernel 0: Wo fp32 -> half
// ---------------------------------------------------------------------------
__global__ __launch_bounds__(256) void conv_wo_kernel(const float* __restrict__ Wo) {
    int i = blockIdx.x * 256 + threadIdx.x;        // 65536 float4s
    float4 w = ((const float4*)Wo)[i];
    uint2 p;
    p.x = f22h(w.x, w.y);
    p.y = f22h(w.z, w.w);
    ((uint2*)g_Woh)[i] = p;
}

// ---------------------------------------------------------------------------
// Kernel 1: projections (tf32 mma), epilogue converts to half.
// grid (NROWS/128, 3), block 128
// ---------------------------------------------------------------------------
__global__ __launch_bounds__(128) void proj_kernel(
    const float* __restrict__ Qin, const float* __restrict__ Kin,
    const float* __restrict__ Vin,
    const float* __restrict__ Wq, const float* __restrict__ Wk,
    const float* __restrict__ Wv)
{
    extern __shared__ float sm[];
    float* Xs = sm;                 // 128 x PITCH
    float* Ws = sm + 128 * PITCH;   // 64 x PITCH

    const int tid  = threadIdx.x;
    const int lane = tid & 31, wm = tid >> 5;
    const int gid  = lane >> 2, qid = lane & 3;
    const int which = blockIdx.y;
    const float* W = (which == 0) ? Wq : (which == 1) ? Wk : Wv;
    const int r0 = blockIdx.x * 128;

    const float4* W4 = (const float4*)W;
    #pragma unroll
    for (int i = 0; i < 8; ++i) {
        int g = tid + i * 128;
        float4 w = W4[g];
        w.x = tf32r(w.x); w.y = tf32r(w.y); w.z = tf32r(w.z); w.w = tf32r(w.w);
        ((float4*)Ws)[(g >> 4) * P4 + (g & 15)] = w;
    }
    if (which < 2) {
        const float4* X4 = (const float4*)((which == 0 ? Qin : Kin) + (size_t)r0 * HD);
        #pragma unroll
        for (int i = 0; i < 16; ++i) {
            int g = tid + i * 128;
            float4 v = X4[g];
            v.x = tf32r(v.x); v.y = tf32r(v.y); v.z = tf32r(v.z); v.w = tf32r(v.w);
            ((float4*)Xs)[(g >> 4) * P4 + (g & 15)] = v;
        }
    } else {
        const int bh = r0 >> 11, l0 = r0 & 2047;
        const int b = bh >> 3, h = bh & 7;
        const float* base = Vin + ((size_t)(b * SEQ + l0)) * EMB + h * HD;
        #pragma unroll
        for (int i = 0; i < 16; ++i) {
            int g = tid + i * 128;
            int r = g >> 4, c4 = g & 15;
            float4 v = *(const float4*)(base + (size_t)r * EMB + c4 * 4);
            v.x = tf32r(v.x); v.y = tf32r(v.y); v.z = tf32r(v.z); v.w = tf32r(v.w);
            ((float4*)Xs)[r * P4 + c4] = v;
        }
    }
    __syncthreads();

    float o[2][8][4];
    #pragma unroll
    for (int mi = 0; mi < 2; ++mi)
        #pragma unroll
        for (int ni = 0; ni < 8; ++ni)
            #pragma unroll
            for (int t = 0; t < 4; ++t) o[mi][ni][t] = 0.f;

    #pragma unroll
    for (int ks = 0; ks < 8; ++ks) {
        float a[2][4];
        #pragma unroll
        for (int mi = 0; mi < 2; ++mi) {
            int r = 32 * wm + 16 * mi + gid;
            int c = ks * 8 + qid;
            a[mi][0] = Xs[r * PITCH + c];
            a[mi][1] = Xs[(r + 8) * PITCH + c];
            a[mi][2] = Xs[r * PITCH + c + 4];
            a[mi][3] = Xs[(r + 8) * PITCH + c + 4];
        }
        #pragma unroll
        for (int ni = 0; ni < 8; ++ni) {
            float b0 = Ws[(ni * 8 + gid) * PITCH + ks * 8 + qid];
            float b1 = Ws[(ni * 8 + gid) * PITCH + ks * 8 + qid + 4];
            #pragma unroll
            for (int mi = 0; mi < 2; ++mi)
                mma8(o[mi][ni][0], o[mi][ni][1], o[mi][ni][2], o[mi][ni][3],
                     a[mi][0], a[mi][1], a[mi][2], a[mi][3], b0, b1);
        }
    }

    // 1/sqrt(512) * log2(e): softmax computed in base-2
    const float qscale = 0.06375863286367196f;
    if (which == 0) {
        #pragma unroll
        for (int mi = 0; mi < 2; ++mi) {
            int r = r0 + 32 * wm + 16 * mi + gid;
            #pragma unroll
            for (int ni = 0; ni < 8; ++ni) {
                int c = ni * 8 + 2 * qid;
                *(uint32_t*)(g_QPh + (size_t)r * HD + c) =
                    f22h(o[mi][ni][0] * qscale, o[mi][ni][1] * qscale);
                *(uint32_t*)(g_QPh + (size_t)(r + 8) * HD + c) =
                    f22h(o[mi][ni][2] * qscale, o[mi][ni][3] * qscale);
            }
        }
    } else if (which == 1) {
        #pragma unroll
        for (int mi = 0; mi < 2; ++mi) {
            int r = r0 + 32 * wm + 16 * mi + gid;
            #pragma unroll
            for (int ni = 0; ni < 8; ++ni) {
                int c = ni * 8 + 2 * qid;
                *(uint32_t*)(g_KPh + (size_t)r * HD + c) = f22h(o[mi][ni][0], o[mi][ni][1]);
                *(uint32_t*)(g_KPh + (size_t)(r + 8) * HD + c) = f22h(o[mi][ni][2], o[mi][ni][3]);
            }
        }
    } else {
        const int bh = r0 >> 11;
        const size_t base = (size_t)bh * HD * SEQ;
        const int l0 = (r0 & 2047);
        #pragma unroll
        for (int mi = 0; mi < 2; ++mi) {
            int l = l0 + 32 * wm + 16 * mi + gid;
            #pragma unroll
            for (int ni = 0; ni < 8; ++ni) {
                int c = ni * 8 + 2 * qid;
                g_VPt[base + (size_t)c * SEQ + l]           = __float2half_rn(o[mi][ni][0]);
                g_VPt[base + (size_t)(c + 1) * SEQ + l]     = __float2half_rn(o[mi][ni][1]);
                g_VPt[base + (size_t)c * SEQ + l + 8]       = __float2half_rn(o[mi][ni][2]);
                g_VPt[base + (size_t)(c + 1) * SEQ + l + 8] = __float2half_rn(o[mi][ni][3]);
            }
        }
    }
}

// ---------------------------------------------------------------------------
// Kernel 2: fp16 flash attention. Br=128, Bc=64. 4 warps m32xn64.
// ldmatrix fragments, exp2 softmax, 3-stage cp.async pipeline.
// grid (SEQ/128, BH), block 128, dyn smem 73728 B
// ---------------------------------------------------------------------------
__global__ __launch_bounds__(128, 2) void attn_kernel()
{
    extern __shared__ __align__(16) unsigned char smraw[];
    __half* Qs = (__half*)smraw;                    // 128 x PH
    __half* KV = (__half*)(smraw + 128 * PH * 2);   // 3 buffers x (K 64xPH + V 64xPH)

    const int tid  = threadIdx.x;
    const int lane = tid & 31, wm = tid >> 5;
    const int gid  = lane >> 2, qid = lane & 3;
    const int bh = blockIdx.y;
    const int q0 = blockIdx.x * 128;

    const uint32_t kv_smem = (uint32_t)__cvta_generic_to_shared(KV);
    const int TILE_H = 64 * PH;
    const int TILE_B = TILE_H * 2;       // 9216 B
    const int NT = SEQ / 64;             // 32

    const __half* Kg0 = g_KPh + (size_t)bh * SEQ * HD;
    const __half* Vg0 = g_VPt + (size_t)bh * HD * SEQ;

    // ldmatrix per-lane byte offset (same geometry for K and V tiles)
    const uint32_t lane_off =
        (uint32_t)((((lane & 7) + ((lane >> 4) << 3)) * PH + ((lane >> 3) & 1) * 8) * 2);

    // prefetch tiles 0, 1
    #pragma unroll
    for (int t = 0; t < 2; ++t) {
        uint32_t base = kv_smem + (uint32_t)(t * 2 * TILE_B);
        #pragma unroll
        for (int i = 0; i < 4; ++i) {
            int g = tid + i * 128;
            int row = g >> 3, c8 = g & 7;
            uint32_t off = (uint32_t)(row * 144 + c8 * 16);
            cp16(base + off, Kg0 + (size_t)(t * 64 + row) * HD + c8 * 8);
            cp16(base + (uint32_t)TILE_B + off, Vg0 + (size_t)row * SEQ + t * 64 + c8 * 8);
        }
        cp_commit();
    }

    // stage Q (pre-scaled half)
    {
        const __half* Qg = g_QPh + (size_t)(bh * SEQ + q0) * HD;
        #pragma unroll
        for (int i = 0; i < 8; ++i) {
            int g = tid + i * 128;
            int row = g >> 3, c8 = g & 7;
            *(float4*)(Qs + row * PH + c8 * 8) = *(const float4*)(Qg + (size_t)row * HD + c8 * 8);
        }
    }
    __syncthreads();

    // Q fragments -> registers
    uint32_t qf[2][4][4];
    #pragma unroll
    for (int mi = 0; mi < 2; ++mi) {
        int r = 32 * wm + 16 * mi + gid;
        #pragma unroll
        for (int kt = 0; kt < 4; ++kt) {
            int c = kt * 16 + 2 * qid;
            qf[mi][kt][0] = *(uint32_t*)&Qs[r * PH + c];
            qf[mi][kt][1] = *(uint32_t*)&Qs[(r + 8) * PH + c];
            qf[mi][kt][2] = *(uint32_t*)&Qs[r * PH + c + 8];
            qf[mi][kt][3] = *(uint32_t*)&Qs[(r + 8) * PH + c + 8];
        }
    }

    float o[2][8][4];
    #pragma unroll
    for (int mi = 0; mi < 2; ++mi)
        #pragma unroll
        for (int ni = 0; ni < 8; ++ni)
            #pragma unroll
            for (int t = 0; t < 4; ++t) o[mi][ni][t] = 0.f;
    float mrow[2][2] = {{-1e30f, -1e30f}, {-1e30f, -1e30f}};
    float lrow[2][2] = {{0.f, 0.f}, {0.f, 0.f}};

    for (int t = 0; t < NT; ++t) {
        if (t == NT - 1) cp_wait0(); else cp_wait1();
        __syncthreads();

        const int buf = t % 3;
        __half* Ks = KV + buf * 2 * TILE_H;
        __half* Vs = Ks + TILE_H;

        if (t + 2 < NT) {
            const int nb = (t + 2) % 3;
            uint32_t base = kv_smem + (uint32_t)(nb * 2 * TILE_B);
            const __half* Kg = Kg0 + (size_t)(t + 2) * 64 * HD;
            const __half* Vg = Vg0 + (t + 2) * 64;
            #pragma unroll
            for (int i = 0; i < 4; ++i) {
                int g = tid + i * 128;
                int row = g >> 3, c8 = g & 7;
                uint32_t off = (uint32_t)(row * 144 + c8 * 16);
                cp16(base + off, Kg + (size_t)row * HD + c8 * 8);
                cp16(base + (uint32_t)TILE_B + off, Vg + (size_t)row * SEQ + c8 * 8);
            }
            cp_commit();
        }

        // ---- S = Q K^T ----
        float sacc[2][8][4];
        #pragma unroll
        for (int mi = 0; mi < 2; ++mi)
            #pragma unroll
            for (int ni = 0; ni < 8; ++ni)
                #pragma unroll
                for (int tt = 0; tt < 4; ++tt) sacc[mi][ni][tt] = 0.f;

        const uint32_t KsS = (uint32_t)__cvta_generic_to_shared(Ks) + lane_off;
        #pragma unroll
        for (int kt = 0; kt < 4; ++kt) {
            #pragma unroll
            for (int nip = 0; nip < 4; ++nip) {
                uint32_t b0, b1, b2, b3;
                ldsm4(b0, b1, b2, b3, KsS + (uint32_t)((nip * 16 * PH + kt * 16) * 2));
                #pragma unroll
                for (int mi = 0; mi < 2; ++mi) {
                    mma16(sacc[mi][2 * nip][0], sacc[mi][2 * nip][1],
                          sacc[mi][2 * nip][2], sacc[mi][2 * nip][3],
                          qf[mi][kt][0], qf[mi][kt][1], qf[mi][kt][2], qf[mi][kt][3], b0, b1);
                    mma16(sacc[mi][2 * nip + 1][0], sacc[mi][2 * nip + 1][1],
                          sacc[mi][2 * nip + 1][2], sacc[mi][2 * nip + 1][3],
                          qf[mi][kt][0], qf[mi][kt][1], qf[mi][kt][2], qf[mi][kt][3], b2, b3);
                }
            }
        }

        // ---- online softmax (base-2, registers) ----
        #pragma unroll
        for (int mi = 0; mi < 2; ++mi) {
            float mx0 = -1e30f, mx1 = -1e30f;
            #pragma unroll
            for (int ni = 0; ni < 8; ++ni) {
                mx0 = fmaxf(mx0, fmaxf(sacc[mi][ni][0], sacc[mi][ni][1]));
                mx1 = fmaxf(mx1, fmaxf(sacc[mi][ni][2], sacc[mi][ni][3]));
            }
            mx0 = fmaxf(mx0, __shfl_xor_sync(0xffffffffu, mx0, 1));
            mx0 = fmaxf(mx0, __shfl_xor_sync(0xffffffffu, mx0, 2));
            mx1 = fmaxf(mx1, __shfl_xor_sync(0xffffffffu, mx1, 1));
            mx1 = fmaxf(mx1, __shfl_xor_sync(0xffffffffu, mx1, 2));

            float mn0 = fmaxf(mrow[mi][0], mx0);
            float mn1 = fmaxf(mrow[mi][1], mx1);
            float c0 = exp2f(mrow[mi][0] - mn0);
            float c1 = exp2f(mrow[mi][1] - mn1);
            mrow[mi][0] = mn0; mrow[mi][1] = mn1;

            float s0 = 0.f, s1 = 0.f;
            #pragma unroll
            for (int ni = 0; ni < 8; ++ni) {
                sacc[mi][ni][0] = exp2f(sacc[mi][ni][0] - mn0);
                sacc[mi][ni][1] = exp2f(sacc[mi][ni][1] - mn0);
                sacc[mi][ni][2] = exp2f(sacc[mi][ni][2] - mn1);
                sacc[mi][ni][3] = exp2f(sacc[mi][ni][3] - mn1);
                s0 += sacc[mi][ni][0] + sacc[mi][ni][1];
                s1 += sacc[mi][ni][2] + sacc[mi][ni][3];
                o[mi][ni][0] *= c0; o[mi][ni][1] *= c0;
                o[mi][ni][2] *= c1; o[mi][ni][3] *= c1;
            }
            s0 += __shfl_xor_sync(0xffffffffu, s0, 1);
            s0 += __shfl_xor_sync(0xffffffffu, s0, 2);
            s1 += __shfl_xor_sync(0xffffffffu, s1, 1);
            s1 += __shfl_xor_sync(0xffffffffu, s1, 2);
            lrow[mi][0] = lrow[mi][0] * c0 + s0;
            lrow[mi][1] = lrow[mi][1] * c1 + s1;
        }

        // ---- O += P V (P packed in regs; C layout == A layout) ----
        const uint32_t VsS = (uint32_t)__cvta_generic_to_shared(Vs) + lane_off;
        #pragma unroll
        for (int kt = 0; kt < 4; ++kt) {
            uint32_t pf[2][4];
            #pragma unroll
            for (int mi = 0; mi < 2; ++mi) {
                pf[mi][0] = f22h(sacc[mi][2 * kt][0],     sacc[mi][2 * kt][1]);
                pf[mi][1] = f22h(sacc[mi][2 * kt][2],     sacc[mi][2 * kt][3]);
                pf[mi][2] = f22h(sacc[mi][2 * kt + 1][0], sacc[mi][2 * kt + 1][1]);
                pf[mi][3] = f22h(sacc[mi][2 * kt + 1][2], sacc[mi][2 * kt + 1][3]);
            }
            #pragma unroll
            for (int nip = 0; nip < 4; ++nip) {
                uint32_t b0, b1, b2, b3;
                ldsm4(b0, b1, b2, b3, VsS + (uint32_t)((nip * 16 * PH + kt * 16) * 2));
                #pragma unroll
                for (int mi = 0; mi < 2; ++mi) {
                    mma16(o[mi][2 * nip][0], o[mi][2 * nip][1],
                          o[mi][2 * nip][2], o[mi][2 * nip][3],
                          pf[mi][0], pf[mi][1], pf[mi][2], pf[mi][3], b0, b1);
                    mma16(o[mi][2 * nip + 1][0], o[mi][2 * nip + 1][1],
                          o[mi][2 * nip + 1][2], o[mi][2 * nip + 1][3],
                          pf[mi][0], pf[mi][1], pf[mi][2], pf[mi][3], b2, b3);
                }
            }
        }
    }

    // epilogue: normalize, store half to g_AOh[b][q][h*64+d]
    const int b = bh >> 3, hh = bh & 7;
    #pragma unroll
    for (int mi = 0; mi < 2; ++mi) {
        int r = 32 * wm + 16 * mi + gid;
        float inv0 = 1.0f / lrow[mi][0];
        float inv1 = 1.0f / lrow[mi][1];
        #pragma unroll
        for (int ni = 0; ni < 8; ++ni) {
            int c = ni * 8 + 2 * qid;
            *(uint32_t*)(g_AOh + (size_t)(b * SEQ + q0 + r) * EMB + hh * HD + c) =
                f22h(o[mi][ni][0] * inv0, o[mi][ni][1] * inv0);
            *(uint32_t*)(g_AOh + (size_t)(b * SEQ + q0 + r + 8) * EMB + hh * HD + c) =
                f22h(o[mi][ni][2] * inv1, o[mi][ni][3] * inv1);
        }
    }
}

// ---------------------------------------------------------------------------
// Kernel 3: out = AOh @ Woh^T + bo  (16384 x 512 x 512), fp16 mma.
// block 256 (8 warps: 4m x 2n), tile m128 x n128, cp.async double buffer.
// grid (128, 4), dyn smem 73728 B
// ---------------------------------------------------------------------------
__global__ __launch_bounds__(256) void out_proj_kernel(
    const float* __restrict__ bo, float* __restrict__ out)
{
    extern __shared__ __align__(16) unsigned char smraw[];
    const int tid  = threadIdx.x;
    const int lane = tid & 31, wid = tid >> 5;
    const int wm = wid >> 1, wn = wid & 1;
    const int gid = lane >> 2, qid = lane & 3;
    const int m0 = blockIdx.x * 128;
    const int n0 = blockIdx.y * 128;

    const uint32_t sm0 = (uint32_t)__cvta_generic_to_shared(smraw);
    const int BUF_B = 2 * 128 * PH * 2;   // As + Bs per buffer = 36864 B

    auto prefetch = [&](int c) {
        uint32_t base = sm0 + (uint32_t)((c & 1) * BUF_B);
        int k0 = c * 64;
        #pragma unroll
        for (int i = 0; i < 4; ++i) {
            int g = tid + i * 256;               // 0..1023
            int row = g >> 3, c8 = g & 7;
            uint32_t off = (uint32_t)(row * 144 + c8 * 16);
            cp16(base + off, g_AOh + (size_t)(m0 + row) * EMB + k0 + c8 * 8);
            cp16(base + (uint32_t)(128 * 144) + off,
                 g_Woh + (size_t)(n0 + row) * EMB + k0 + c8 * 8);
        }
        cp_commit();
    };

    prefetch(0);

    float o[2][8][4];
    #pragma unroll
    for (int mi = 0; mi < 2; ++mi)
        #pragma unroll
        for (int ni = 0; ni < 8; ++ni)
            #pragma unroll
            for (int t = 0; t < 4; ++t) o[mi][ni][t] = 0.f;

    const uint32_t laneA = (uint32_t)(((lane & 15) * PH + (lane >> 4) * 8) * 2);
    const uint32_t laneB =
        (uint32_t)((((lane & 7) + ((lane >> 4) << 3)) * PH + ((lane >> 3) & 1) * 8) * 2);

    for (int c = 0; c < 8; ++c) {
        cp_wait0();
        __syncthreads();
        if (c + 1 < 8) prefetch(c + 1);

        uint32_t AsS = sm0 + (uint32_t)((c & 1) * BUF_B) + laneA;
        uint32_t BsS = sm0 + (uint32_t)((c & 1) * BUF_B + 128 * 144) + laneB;

        #pragma unroll
        for (int kt = 0; kt < 4; ++kt) {
            uint32_t a[2][4];
            #pragma unroll
            for (int mi = 0; mi < 2; ++mi)
                ldsm4(a[mi][0], a[mi][1], a[mi][2], a[mi][3],
                      AsS + (uint32_t)((((32 * wm + 16 * mi) * PH) + kt * 16) * 2));
            #pragma unroll
            for (int nip = 0; nip < 4; ++nip) {
                uint32_t b0, b1, b2, b3;
                ldsm4(b0, b1, b2, b3,
                      BsS + (uint32_t)((((64 * wn + nip * 16) * PH) + kt * 16) * 2));
                #pragma unroll
                for (int mi = 0; mi < 2; ++mi) {
                    mma16(o[mi][2 * nip][0], o[mi][2 * nip][1],
                          o[mi][2 * nip][2], o[mi][2 * nip][3],
                          a[mi][0], a[mi][1], a[mi][2], a[mi][3], b0, b1);
                    mma16(o[mi][2 * nip + 1][0], o[mi][2 * nip + 1][1],
                          o[mi][2 * nip + 1][2], o[mi][2 * nip + 1][3],
                          a[mi][0], a[mi][1], a[mi][2], a[mi][3], b2, b3);
                }
            }
        }
    }

    #pragma unroll
    for (int mi = 0; mi < 2; ++mi) {
        int r = m0 + 32 * wm + 16 * mi + gid;
        #pragma unroll
        for (int ni = 0; ni < 8; ++ni) {
            int cc = n0 + 64 * wn + ni * 8 + 2 * qid;
            float bb0 = bo[cc], bb1 = bo[cc + 1];
            *(float2*)(out + (size_t)r * EMB + cc) =
                make_float2(o[mi][ni][0] + bb0, o[mi][ni][1] + bb1);
            *(float2*)(out + (size_t)(r + 8) * EMB + cc) =
                make_float2(o[mi][ni][2] + bb0, o[mi][ni][3] + bb1);
        }
    }
}

// ---------------------------------------------------------------------------
extern "C" void kernel_launch(void* const* d_in, const int* in_sizes, int n_in,
                              void* d_out, int out_size)
{
    const float* q  = (const float*)d_in[0];
    const float* k  = (const float*)d_in[1];
    const float* v  = (const float*)d_in[2];
    const float* Wq = (const float*)d_in[3];
    const float* Wk = (const float*)d_in[4];
    const float* Wv = (const float*)d_in[5];
    const float* Wo = (const float*)d_in[6];
    const float* bo = (const float*)d_in[7];
    float* out = (float*)d_out;

    const int proj_smem  = (128 * PITCH + 64 * PITCH) * (int)sizeof(float);   // 52224
    const int attn_smem  = (128 * PH + 3 * 2 * 64 * PH) * 2;                  // 73728
    const int oproj_smem = 2 * 2 * 128 * PH * 2;                              // 73728

    cudaFuncSetAttribute(proj_kernel, cudaFuncAttributeMaxDynamicSharedMemorySize, proj_smem);
    cudaFuncSetAttribute(attn_kernel, cudaFuncAttributeMaxDynamicSharedMemorySize, attn_smem);
    cudaFuncSetAttribute(out_proj_kernel, cudaFuncAttributeMaxDynamicSharedMemorySize, oproj_smem);

    conv_wo_kernel<<<256, 256>>>(Wo);
    proj_kernel<<<dim3(NROWS / 128, 3, 1), 128, proj_smem>>>(q, k, v, Wq, Wk, Wv);
    attn_kernel<<<dim3(SEQ / 128, BH, 1), 128, attn_smem>>>();
    out_proj_kernel<<<dim3((NB * SEQ) / 128, EMB / 128, 1), 256, oproj_smem>>>(bo, out);
}